// round 6
// baseline (speedup 1.0000x reference)
#include <cuda_runtime.h>

// FWHT-128 over the last dim of three (4,32,4096,128) fp32 tensors.
// Mapping: 8 lanes per row (j = lane&7), each thread handles TWO rows:
//   rowA = warp*8 + (lane>>3),  rowB = rowA + 4.
// Per row a thread owns 16 floats as 4 float4s at float4-indices
// {j, j+8, j+16, j+24}. Every warp-LDG.128 covers 4 complete 128B lines
// (full-line coalescing) and there are 8 front-batched loads (MLP=8).
//   In-register stages: h=1,2 (inside float4), h=32,64 (across the 4 float4s).
//   Shuffle stages:     h=4,8,16 -> __shfl_xor masks 1,2,4 (within 8-lane group).

__global__ __launch_bounds__(256) void fwht128_kernel(
    const float4* __restrict__ q,
    const float4* __restrict__ k,
    const float4* __restrict__ v,
    float4* __restrict__ out,
    int rowsPerArr)
{
    const int lane = threadIdx.x & 31;
    const int warpGlobal = (int)((blockIdx.x * blockDim.x + threadIdx.x) >> 5);
    const int rowA = warpGlobal * 8 + (lane >> 3);
    if (rowA + 4 >= rowsPerArr + 4) return;          // rowsPerArr multiple of 8; keep guard cheap
    const int rowB = rowA + 4;

    const float4* __restrict__ src = (blockIdx.y == 0) ? q : (blockIdx.y == 1) ? k : v;

    const size_t baseA = (size_t)rowA * 32 + (lane & 7);
    const size_t baseB = (size_t)rowB * 32 + (lane & 7);

    // 8 front-batched full-line loads (MLP = 8), streaming hint.
    float4 a0 = __ldcs(src + baseA);
    float4 a1 = __ldcs(src + baseA + 8);
    float4 a2 = __ldcs(src + baseA + 16);
    float4 a3 = __ldcs(src + baseA + 24);
    float4 b0 = __ldcs(src + baseB);
    float4 b1 = __ldcs(src + baseB + 8);
    float4 b2 = __ldcs(src + baseB + 16);
    float4 b3 = __ldcs(src + baseB + 24);

    // ---- Stage h=1: pairs (x,y),(z,w) inside each float4 ----
    #define STAGE_H1(f) { float ta=f.x, tb=f.y, tc=f.z, td=f.w; \
        f.x=ta+tb; f.y=ta-tb; f.z=tc+td; f.w=tc-td; }
    STAGE_H1(a0) STAGE_H1(a1) STAGE_H1(a2) STAGE_H1(a3)
    STAGE_H1(b0) STAGE_H1(b1) STAGE_H1(b2) STAGE_H1(b3)

    // ---- Stage h=2: pairs (x,z),(y,w) inside each float4 ----
    #define STAGE_H2(f) { float ta=f.x, tb=f.z, tc=f.y, td=f.w; \
        f.x=ta+tb; f.z=ta-tb; f.y=tc+td; f.w=tc-td; }
    STAGE_H2(a0) STAGE_H2(a1) STAGE_H2(a2) STAGE_H2(a3)
    STAGE_H2(b0) STAGE_H2(b1) STAGE_H2(b2) STAGE_H2(b3)

    // ---- Stages h=4,8,16: partner lane = lane ^ m, m in {1,2,4} ----
    // val_new = p + sgn*val  (sgn=+1 low side, -1 high side)
    #pragma unroll
    for (int m = 1; m <= 4; m <<= 1) {
        const float sgn = (lane & m) ? -1.0f : 1.0f;
        #define SHFL_BF(val) { \
            float p = __shfl_xor_sync(0xffffffffu, val, m); \
            val = fmaf(val, sgn, p); }
        SHFL_BF(a0.x) SHFL_BF(a0.y) SHFL_BF(a0.z) SHFL_BF(a0.w)
        SHFL_BF(a1.x) SHFL_BF(a1.y) SHFL_BF(a1.z) SHFL_BF(a1.w)
        SHFL_BF(a2.x) SHFL_BF(a2.y) SHFL_BF(a2.z) SHFL_BF(a2.w)
        SHFL_BF(a3.x) SHFL_BF(a3.y) SHFL_BF(a3.z) SHFL_BF(a3.w)
        SHFL_BF(b0.x) SHFL_BF(b0.y) SHFL_BF(b0.z) SHFL_BF(b0.w)
        SHFL_BF(b1.x) SHFL_BF(b1.y) SHFL_BF(b1.z) SHFL_BF(b1.w)
        SHFL_BF(b2.x) SHFL_BF(b2.y) SHFL_BF(b2.z) SHFL_BF(b2.w)
        SHFL_BF(b3.x) SHFL_BF(b3.y) SHFL_BF(b3.z) SHFL_BF(b3.w)
        #undef SHFL_BF
    }

    // ---- Pair butterfly across float4s ----
    #define BF_PAIR(p, r) { float t; \
        t=p.x; p.x=t+r.x; r.x=t-r.x; \
        t=p.y; p.y=t+r.y; r.y=t-r.y; \
        t=p.z; p.z=t+r.z; r.z=t-r.z; \
        t=p.w; p.w=t+r.w; r.w=t-r.w; }

    // Stage h=32: (f0,f1),(f2,f3) within each row
    BF_PAIR(a0, a1) BF_PAIR(a2, a3)
    BF_PAIR(b0, b1) BF_PAIR(b2, b3)
    // Stage h=64: (f0,f2),(f1,f3) within each row
    BF_PAIR(a0, a2) BF_PAIR(a1, a3)
    BF_PAIR(b0, b2) BF_PAIR(b1, b3)

    // ---- Scale by 1/sqrt(128) ----
    const float s = 0.08838834764831845f;
    #define SCALE(f) { f.x*=s; f.y*=s; f.z*=s; f.w*=s; }
    SCALE(a0) SCALE(a1) SCALE(a2) SCALE(a3)
    SCALE(b0) SCALE(b1) SCALE(b2) SCALE(b3)

    float4* __restrict__ dst = out + (size_t)blockIdx.y * rowsPerArr * 32;
    __stcs(dst + baseA,      a0);
    __stcs(dst + baseA + 8,  a1);
    __stcs(dst + baseA + 16, a2);
    __stcs(dst + baseA + 24, a3);
    __stcs(dst + baseB,      b0);
    __stcs(dst + baseB + 8,  b1);
    __stcs(dst + baseB + 16, b2);
    __stcs(dst + baseB + 24, b3);
}

extern "C" void kernel_launch(void* const* d_in, const int* in_sizes, int n_in,
                              void* d_out, int out_size)
{
    const float4* q = (const float4*)d_in[0];
    const float4* k = (const float4*)d_in[1];
    const float4* v = (const float4*)d_in[2];
    float4* out = (float4*)d_out;

    const int rowsPerArr = in_sizes[0] / 128;   // 524288 (multiple of 64)
    const int rowsPerBlock = (256 / 32) * 8;    // 8 warps * 8 rows = 64
    const int blocksX = (rowsPerArr + rowsPerBlock - 1) / rowsPerBlock;

    dim3 grid(blocksX, 3, 1);
    fwht128_kernel<<<grid, 256>>>(q, k, v, out, rowsPerArr);
}

// round 7
// speedup vs baseline: 1.0007x; 1.0007x over previous
#include <cuda_runtime.h>

// FWHT-128 over the last dim of three (4,32,4096,128) fp32 tensors.
// R4 mapping (best measured): 8 lanes per row, 4 rows per warp; each thread
// owns 16 floats of one row as 4 float4s at float4-indices {j, j+8, j+16, j+24}
// (j = lane&7). Every warp-LDG.128 covers 4 complete 128B lines; 4
// front-batched loads (MLP=4); streaming cache hints.
//   In-register stages: h=1,2 (inside float4), h=32,64 (across the 4 float4s).
//   Shuffle stages:     h=4,8,16 -> __shfl_xor masks 1,2,4 (within 8-lane group).
// Flat 1-D grid; arrays q/k/v interleaved across consecutive blocks (bid % 3)
// so every wave streams all three buffers. No guard (exact division).

__global__ __launch_bounds__(256, 8) void fwht128_kernel(
    const float4* __restrict__ q,
    const float4* __restrict__ k,
    const float4* __restrict__ v,
    float4* __restrict__ out,
    int rowsPerArr)
{
    const int bid = blockIdx.x;
    const int arr = bid % 3;                   // which tensor
    const int blkInArr = bid / 3;              // block index within that tensor

    const int lane = threadIdx.x & 31;
    const int warpInBlk = threadIdx.x >> 5;    // 0..7
    // 8 warps/block * 4 rows/warp = 32 rows per block
    const int row = blkInArr * 32 + warpInBlk * 4 + (lane >> 3);

    const float4* __restrict__ src = (arr == 0) ? q : (arr == 1) ? k : v;

    const size_t base = (size_t)row * 32 + (lane & 7);

    // Front-batched full-line loads (MLP = 4), streaming hint.
    float4 f0 = __ldcs(src + base);
    float4 f1 = __ldcs(src + base + 8);
    float4 f2 = __ldcs(src + base + 16);
    float4 f3 = __ldcs(src + base + 24);

    // ---- Stage h=1: pairs (x,y),(z,w) inside each float4 ----
    #define STAGE_H1(f) { float ta=f.x, tb=f.y, tc=f.z, td=f.w; \
        f.x=ta+tb; f.y=ta-tb; f.z=tc+td; f.w=tc-td; }
    STAGE_H1(f0) STAGE_H1(f1) STAGE_H1(f2) STAGE_H1(f3)

    // ---- Stage h=2: pairs (x,z),(y,w) inside each float4 ----
    #define STAGE_H2(f) { float ta=f.x, tb=f.z, tc=f.y, td=f.w; \
        f.x=ta+tb; f.z=ta-tb; f.y=tc+td; f.w=tc-td; }
    STAGE_H2(f0) STAGE_H2(f1) STAGE_H2(f2) STAGE_H2(f3)

    // ---- Stages h=4,8,16: partner lane = lane ^ m, m in {1,2,4} ----
    // val_new = p + sgn*val  (sgn=+1 low side, -1 high side)
    #pragma unroll
    for (int m = 1; m <= 4; m <<= 1) {
        const float sgn = (lane & m) ? -1.0f : 1.0f;
        #define SHFL_BF(val) { \
            float p = __shfl_xor_sync(0xffffffffu, val, m); \
            val = fmaf(val, sgn, p); }
        SHFL_BF(f0.x) SHFL_BF(f0.y) SHFL_BF(f0.z) SHFL_BF(f0.w)
        SHFL_BF(f1.x) SHFL_BF(f1.y) SHFL_BF(f1.z) SHFL_BF(f1.w)
        SHFL_BF(f2.x) SHFL_BF(f2.y) SHFL_BF(f2.z) SHFL_BF(f2.w)
        SHFL_BF(f3.x) SHFL_BF(f3.y) SHFL_BF(f3.z) SHFL_BF(f3.w)
        #undef SHFL_BF
    }

    // ---- Pair butterfly across float4s ----
    #define BF_PAIR(p, r) { float t; \
        t=p.x; p.x=t+r.x; r.x=t-r.x; \
        t=p.y; p.y=t+r.y; r.y=t-r.y; \
        t=p.z; p.z=t+r.z; r.z=t-r.z; \
        t=p.w; p.w=t+r.w; r.w=t-r.w; }

    // Stage h=32: (f0,f1),(f2,f3)
    BF_PAIR(f0, f1) BF_PAIR(f2, f3)
    // Stage h=64: (f0,f2),(f1,f3)
    BF_PAIR(f0, f2) BF_PAIR(f1, f3)

    // ---- Scale by 1/sqrt(128) ----
    const float s = 0.08838834764831845f;
    #define SCALE(f) { f.x*=s; f.y*=s; f.z*=s; f.w*=s; }
    SCALE(f0) SCALE(f1) SCALE(f2) SCALE(f3)

    float4* __restrict__ dst = out + (size_t)arr * rowsPerArr * 32;
    __stcs(dst + base,      f0);
    __stcs(dst + base + 8,  f1);
    __stcs(dst + base + 16, f2);
    __stcs(dst + base + 24, f3);
}

extern "C" void kernel_launch(void* const* d_in, const int* in_sizes, int n_in,
                              void* d_out, int out_size)
{
    const float4* q = (const float4*)d_in[0];
    const float4* k = (const float4*)d_in[1];
    const float4* v = (const float4*)d_in[2];
    float4* out = (float4*)d_out;

    const int rowsPerArr = in_sizes[0] / 128;        // 524288 (multiple of 32)
    const int rowsPerBlock = 32;                     // 8 warps * 4 rows
    const int blocksPerArr = rowsPerArr / rowsPerBlock;

    fwht128_kernel<<<blocksPerArr * 3, 256>>>(q, k, v, out, rowsPerArr);
}

// round 8
// speedup vs baseline: 1.0052x; 1.0045x over previous
#include <cuda_runtime.h>

// FWHT-128 over the last dim of three (4,32,4096,128) fp32 tensors.
// 256-bit (v8.f32) global loads/stores — sm_100+ LDG.E.256/STG.E.256.
// Mapping: 8 lanes per row (j = lane&7), 4 rows per warp. Each thread owns
// two contiguous 8-float chunks of its row: elements {8j..8j+7} and
// {64+8j..64+8j+7} (32-byte aligned).
//   In-register stages: h=1,2,4 (inside each 8-float chunk), h=64 (between chunks).
//   Shuffle stages:     h=8,16,32 -> __shfl_xor masks 1,2,4 (within 8-lane group).

__device__ __forceinline__ void ldg256_cs(const float* p, float* r) {
    asm volatile("ld.global.cs.v8.f32 {%0,%1,%2,%3,%4,%5,%6,%7}, [%8];"
        : "=f"(r[0]), "=f"(r[1]), "=f"(r[2]), "=f"(r[3]),
          "=f"(r[4]), "=f"(r[5]), "=f"(r[6]), "=f"(r[7])
        : "l"(p));
}

__device__ __forceinline__ void stg256_cs(float* p, const float* r) {
    asm volatile("st.global.cs.v8.f32 [%0], {%1,%2,%3,%4,%5,%6,%7,%8};"
        :: "l"(p),
           "f"(r[0]), "f"(r[1]), "f"(r[2]), "f"(r[3]),
           "f"(r[4]), "f"(r[5]), "f"(r[6]), "f"(r[7])
        : "memory");
}

__global__ __launch_bounds__(256) void fwht128_kernel(
    const float* __restrict__ q,
    const float* __restrict__ k,
    const float* __restrict__ v,
    float* __restrict__ out,
    int rowsPerArr)
{
    const int lane = threadIdx.x & 31;
    const int warpGlobal = (int)((blockIdx.x * blockDim.x + threadIdx.x) >> 5);
    const int row = warpGlobal * 4 + (lane >> 3);
    const int j = lane & 7;

    const float* __restrict__ src = (blockIdx.y == 0) ? q : (blockIdx.y == 1) ? k : v;

    const size_t base = (size_t)row * 128 + j * 8;   // float index, 32B-aligned

    float c0[8], c1[8];
    ldg256_cs(src + base,      c0);   // elements 8j+0..7
    ldg256_cs(src + base + 64, c1);   // elements 64+8j+0..7

    // ---- In-chunk stages h=1,2,4 on each 8-float chunk ----
    #define CHUNK_H1(c) { float a; \
        a=c[0]; c[0]=a+c[1]; c[1]=a-c[1]; \
        a=c[2]; c[2]=a+c[3]; c[3]=a-c[3]; \
        a=c[4]; c[4]=a+c[5]; c[5]=a-c[5]; \
        a=c[6]; c[6]=a+c[7]; c[7]=a-c[7]; }
    #define CHUNK_H2(c) { float a; \
        a=c[0]; c[0]=a+c[2]; c[2]=a-c[2]; \
        a=c[1]; c[1]=a+c[3]; c[3]=a-c[3]; \
        a=c[4]; c[4]=a+c[6]; c[6]=a-c[6]; \
        a=c[5]; c[5]=a+c[7]; c[7]=a-c[7]; }
    #define CHUNK_H4(c) { float a; \
        a=c[0]; c[0]=a+c[4]; c[4]=a-c[4]; \
        a=c[1]; c[1]=a+c[5]; c[5]=a-c[5]; \
        a=c[2]; c[2]=a+c[6]; c[6]=a-c[6]; \
        a=c[3]; c[3]=a+c[7]; c[7]=a-c[7]; }
    CHUNK_H1(c0) CHUNK_H1(c1)
    CHUNK_H2(c0) CHUNK_H2(c1)
    CHUNK_H4(c0) CHUNK_H4(c1)

    // ---- Stages h=8,16,32: element bits 3,4,5 live in j -> masks 1,2,4 ----
    // val_new = p + sgn*val  (sgn=+1 low side, -1 high side)
    #pragma unroll
    for (int m = 1; m <= 4; m <<= 1) {
        const float sgn = (j & m) ? -1.0f : 1.0f;
        #pragma unroll
        for (int i = 0; i < 8; i++) {
            float p = __shfl_xor_sync(0xffffffffu, c0[i], m);
            c0[i] = fmaf(c0[i], sgn, p);
        }
        #pragma unroll
        for (int i = 0; i < 8; i++) {
            float p = __shfl_xor_sync(0xffffffffu, c1[i], m);
            c1[i] = fmaf(c1[i], sgn, p);
        }
    }

    // ---- Stage h=64: between the two chunks; fold in final 1/sqrt(128) scale ----
    const float s = 0.08838834764831845f;
    #pragma unroll
    for (int i = 0; i < 8; i++) {
        float a = c0[i];
        c0[i] = (a + c1[i]) * s;
        c1[i] = (a - c1[i]) * s;
    }

    float* __restrict__ dst = out + (size_t)blockIdx.y * rowsPerArr * 128;
    stg256_cs(dst + base,      c0);
    stg256_cs(dst + base + 64, c1);
}

extern "C" void kernel_launch(void* const* d_in, const int* in_sizes, int n_in,
                              void* d_out, int out_size)
{
    const float* q = (const float*)d_in[0];
    const float* k = (const float*)d_in[1];
    const float* v = (const float*)d_in[2];
    float* out = (float*)d_out;

    const int rowsPerArr = in_sizes[0] / 128;   // 524288 (multiple of 32)
    const int rowsPerBlock = (256 / 32) * 4;    // 8 warps * 4 rows = 32
    const int blocksX = rowsPerArr / rowsPerBlock;

    dim3 grid(blocksX, 3, 1);
    fwht128_kernel<<<grid, 256>>>(q, k, v, out, rowsPerArr);
}